// round 13
// baseline (speedup 1.0000x reference)
#include <cuda_runtime.h>
#include <cstdint>

#define Bc    524288
#define HID   64
#define NSTEP 10

typedef unsigned long long ull;

// Scratch: c_pre = b1 + context @ W1[2:66], layout [q][B] as float4 (q = neuron/4)
__device__ float4 g_cpre[16 * Bc];

// ---------- packed f32x2 helpers ----------
__device__ __forceinline__ ull pk2(float a, float b) {
    ull r; asm("mov.b64 %0, {%1, %2};" : "=l"(r) : "f"(a), "f"(b)); return r;
}
__device__ __forceinline__ void up2(ull v, float& a, float& b) {
    asm("mov.b64 {%0, %1}, %2;" : "=f"(a), "=f"(b) : "l"(v));
}
__device__ __forceinline__ ull ffma2(ull a, ull b, ull c) {
    ull d; asm("fma.rn.f32x2 %0, %1, %2, %3;" : "=l"(d) : "l"(a), "l"(b), "l"(c)); return d;
}
__device__ __forceinline__ ull fmul2(ull a, ull b) {
    ull d; asm("mul.rn.f32x2 %0, %1, %2;" : "=l"(d) : "l"(a), "l"(b)); return d;
}
__device__ __forceinline__ ull fadd2(ull a, ull b) {
    ull d; asm("add.rn.f32x2 %0, %1, %2;" : "=l"(d) : "l"(a), "l"(b)); return d;
}
__device__ __forceinline__ ull L64(const float* p) {        // LDS.64
    return *reinterpret_cast<const ull*>(p);
}
// tanh(x) = 1 - 2/(1 + exp(2x)); ex2.approx + rcp.approx. ~1e-7 abs err, saturates safely.
__device__ __forceinline__ float ftanh(float x) {
    float e; asm("ex2.approx.f32 %0, %1;" : "=f"(e) : "f"(x * 2.885390081777927f));
    float r; asm("rcp.approx.f32 %0, %1;" : "=f"(r) : "f"(e + 1.0f));
    return fmaf(-2.0f, r, 1.0f);
}

// ---------- Kernel A: c_pre precompute (context part of layer 1, done once) ----------
__global__ __launch_bounds__(256) void cnf_pre(
    const float* __restrict__ ctx, const float* __restrict__ W1,
    const float* __restrict__ b1)
{
    __shared__ __align__(16) float sW1c[64 * 64];  // W1 rows 2..65
    __shared__ float sb1[64];
    const int tid = threadIdx.x;
    for (int i = tid; i < 4096; i += 256) sW1c[i] = W1[2 * 64 + i];
    if (tid < 64) sb1[tid] = b1[tid];
    __syncthreads();

    const int b = blockIdx.x * 256 + tid;
    float cx[64];
    const float4* c4 = reinterpret_cast<const float4*>(ctx + (size_t)b * 64);
#pragma unroll
    for (int q = 0; q < 16; q++) {
        float4 v = __ldg(&c4[q]);
        cx[4 * q] = v.x; cx[4 * q + 1] = v.y; cx[4 * q + 2] = v.z; cx[4 * q + 3] = v.w;
    }
#pragma unroll 1
    for (int q = 0; q < 16; q++) {
        float4 a = make_float4(sb1[4 * q], sb1[4 * q + 1], sb1[4 * q + 2], sb1[4 * q + 3]);
#pragma unroll
        for (int c = 0; c < 64; c++) {
            const float4 w = *reinterpret_cast<const float4*>(&sW1c[(c << 6) + 4 * q]);
            a.x = fmaf(cx[c], w.x, a.x);
            a.y = fmaf(cx[c], w.y, a.y);
            a.z = fmaf(cx[c], w.z, a.z);
            a.w = fmaf(cx[c], w.w, a.w);
        }
        g_cpre[(size_t)q * Bc + b] = a;
    }
}

// ---------- Kernel B: RK4 CNF, forward-mode (JVP) Hutchinson, 4-way j-split ----------
// div = e^T (J e) via tangent propagation (one W2 pass per j-quarter):
//   s1[m]  = e0*W1[0,m] + e1*W1[1,m]
//   th1[m] = (1 - h1[m]^2) * s1[m]
//   u2[j]  = sum_m h1[m]*W2[m,j] ; t2[j] = sum_m th1[m]*W2[m,j]
//   f = tanh(u2)@W3 + b3 ;  Je = ((1-tanh(u2)^2)*t2)@W3 ;  div = e.Je
// j processed in 4 quarters of 16 so the packed accumulator file is 8+8 ull
// (32 regs), capping the kernel at 128 regs -> 4 CTAs/SM (full 64K-reg file).
// Layer 1 recomputed per quarter (cheap; c_pre LDGs are L1 hits).
__global__ __launch_bounds__(128, 4) void cnf_main(
    const float* __restrict__ x, const float* __restrict__ eps,
    const float* __restrict__ W1, const float* __restrict__ W2,
    const float* __restrict__ b2, const float* __restrict__ W3,
    const float* __restrict__ b3, float* __restrict__ out)
{
    __shared__ __align__(16) float sW2[64 * 64];   // [m][j]
    __shared__ __align__(16) float sW1r0[64];      // W1[0][j]
    __shared__ __align__(16) float sW1r1[64];      // W1[1][j]
    __shared__ __align__(16) float sW1t[64];       // W1[66][j]
    __shared__ __align__(16) float sb2[64];
    __shared__ __align__(16) float sW3[128];       // interleaved {W3[j][0], W3[j][1]}

    const int tid = threadIdx.x;
    {
        float4* d = reinterpret_cast<float4*>(sW2);
        const float4* s = reinterpret_cast<const float4*>(W2);
        for (int i = tid; i < 1024; i += 128) d[i] = s[i];
    }
    if (tid < 64) {
        sW1r0[tid] = W1[tid];
        sW1r1[tid] = W1[64 + tid];
        sW1t[tid]  = W1[66 * 64 + tid];
        sb2[tid]   = b2[tid];
        sW3[2 * tid]     = W3[2 * tid];
        sW3[2 * tid + 1] = W3[2 * tid + 1];
    }
    __syncthreads();

    const float bo0 = __ldg(&b3[0]), bo1 = __ldg(&b3[1]);
    const int b = blockIdx.x * 128 + tid;

    float z0 = x[2 * b], z1 = x[2 * b + 1], lp = 0.0f;
    const float step = -1.0f / 9.0f;

#pragma unroll 1
    for (int s = 0; s < NSTEP - 1; s++) {
        const float ti = 1.0f + s * step;
        const float hh = (1.0f + (s + 1) * step) - ti;
        float az0 = 0.f, az1 = 0.f, al = 0.f;
        float zi0 = z0, zi1 = z1;

#pragma unroll 1
        for (int k = 0; k < 4; k++) {
            const float tk = ti + ((k == 0) ? 0.0f : ((k == 3) ? hh : 0.5f * hh));
            const float2 ev = __ldg(reinterpret_cast<const float2*>(
                eps + (((size_t)(s * 4 + k)) * Bc + b) * 2));
            const float e0 = ev.x, e1 = ev.y;

            const ull z0d = pk2(zi0, zi0);
            const ull z1d = pk2(zi1, zi1);
            const ull tdp = pk2(tk, tk);
            const ull e0d = pk2(e0, e0);
            const ull e1d = pk2(e1, e1);

            ull fa0 = 0ULL, fa1 = 0ULL, ja0 = 0ULL, ja1 = 0ULL;

#pragma unroll 1
            for (int jh = 0; jh < 4; jh++) {
                const int jo = jh << 4;              // j offset (floats) of this quarter
                const float* w2h = sW2 + jo;

                // packed j-pair accumulators for this quarter: value + tangent
                ull accu[8], acct[8];
#pragma unroll
                for (int p = 0; p < 8; p++) {
                    accu[p] = L64(sb2 + jo + 2 * p);
                    acct[p] = 0ULL;
                }

                // fused layer 1 (recomputed per quarter) + rank-1 updates
#pragma unroll 1
                for (int q = 0; q < 16; q++) {
                    const float4 cp = __ldg(&g_cpre[(size_t)q * Bc + b]);
                    const ull r0a = L64(sW1r0 + 4 * q), r0b = L64(sW1r0 + 4 * q + 2);
                    const ull r1a = L64(sW1r1 + 4 * q), r1b = L64(sW1r1 + 4 * q + 2);
                    const ull tta = L64(sW1t  + 4 * q), ttb = L64(sW1t  + 4 * q + 2);
                    ull p0 = pk2(cp.x, cp.y), p1 = pk2(cp.z, cp.w);
                    p0 = ffma2(z0d, r0a, p0);  p1 = ffma2(z0d, r0b, p1);
                    p0 = ffma2(z1d, r1a, p0);  p1 = ffma2(z1d, r1b, p1);
                    p0 = ffma2(tdp, tta, p0);  p1 = ffma2(tdp, ttb, p1);
                    // layer-1 tangent: s1 = e0*W1r0 + e1*W1r1 (same operands)
                    ull sa = fmul2(e0d, r0a);  sa = ffma2(e1d, r1a, sa);
                    ull sb = fmul2(e0d, r0b);  sb = ffma2(e1d, r1b, sb);

                    float u4[4], s4[4];
                    up2(p0, u4[0], u4[1]); up2(p1, u4[2], u4[3]);
                    up2(sa, s4[0], s4[1]); up2(sb, s4[2], s4[3]);

#pragma unroll
                    for (int r = 0; r < 4; r++) {
                        const int m = 4 * q + r;
                        const float h  = ftanh(u4[r]);
                        const float th = s4[r] * fmaf(-h, h, 1.0f);
                        const ull hd  = pk2(h, h);
                        const ull thd = pk2(th, th);
                        const ulonglong2* wr =
                            reinterpret_cast<const ulonglong2*>(w2h + (m << 6));
#pragma unroll
                        for (int p = 0; p < 4; p++) {
                            const ulonglong2 wv = wr[p];    // LDS.128 broadcast
                            accu[2 * p]     = ffma2(hd,  wv.x, accu[2 * p]);
                            accu[2 * p + 1] = ffma2(hd,  wv.y, accu[2 * p + 1]);
                            acct[2 * p]     = ffma2(thd, wv.x, acct[2 * p]);
                            acct[2 * p + 1] = ffma2(thd, wv.y, acct[2 * p + 1]);
                        }
                    }
                }

                // output-layer epilogue for this quarter
                const float* w3h = sW3 + 2 * jo;
#pragma unroll
                for (int p = 0; p < 8; p++) {
                    float ua, ub; up2(accu[p], ua, ub);
                    float ta, tb; up2(acct[p], ta, tb);
                    const float ha = ftanh(ua), hb = ftanh(ub);
                    const float ca = ta * fmaf(-ha, ha, 1.0f);
                    const float cb = tb * fmaf(-hb, hb, 1.0f);
                    const ull w3a = L64(w3h + 4 * p);
                    const ull w3b = L64(w3h + 4 * p + 2);
                    fa0 = ffma2(pk2(ha, ha), w3a, fa0);
                    fa1 = ffma2(pk2(hb, hb), w3b, fa1);
                    ja0 = ffma2(pk2(ca, ca), w3a, ja0);
                    ja1 = ffma2(pk2(cb, cb), w3b, ja1);
                }
            }

            float f0, f1; up2(fadd2(fa0, fa1), f0, f1);
            f0 += bo0; f1 += bo1;
            float je0, je1; up2(fadd2(ja0, ja1), je0, je1);
            const float nd = -(je0 * e0 + je1 * e1);    // -divergence

            // ===== RK4 bookkeeping
            const float wk = (k == 1 || k == 2) ? 2.0f : 1.0f;
            az0 = fmaf(wk, f0, az0);
            az1 = fmaf(wk, f1, az1);
            al  = fmaf(wk, nd, al);
            const float cin = (k == 2) ? hh : 0.5f * hh;
            zi0 = fmaf(cin, f0, z0);
            zi1 = fmaf(cin, f1, z1);
        }
        const float c6 = hh * (1.0f / 6.0f);
        z0 = fmaf(c6, az0, z0);
        z1 = fmaf(c6, az1, z1);
        lp = fmaf(c6, al, lp);
    }

    out[2 * b]      = z0;
    out[2 * b + 1]  = z1;
    out[2 * Bc + b] = lp;          // lp1 follows flattened z1
}

extern "C" void kernel_launch(void* const* d_in, const int* in_sizes, int n_in,
                              void* d_out, int out_size)
{
    (void)in_sizes; (void)n_in; (void)out_size;
    const float* x   = (const float*)d_in[0];
    const float* ctx = (const float*)d_in[1];
    const float* eps = (const float*)d_in[2];
    const float* W1  = (const float*)d_in[3];
    const float* b1  = (const float*)d_in[4];
    const float* W2  = (const float*)d_in[5];
    const float* b2  = (const float*)d_in[6];
    const float* W3  = (const float*)d_in[7];
    const float* b3  = (const float*)d_in[8];
    float* out = (float*)d_out;

    cnf_pre<<<Bc / 256, 256>>>(ctx, W1, b1);
    cnf_main<<<Bc / 128, 128>>>(x, eps, W1, W2, b2, W3, b3, out);
}

// round 14
// speedup vs baseline: 1.2015x; 1.2015x over previous
#include <cuda_runtime.h>
#include <cstdint>

#define Bc    524288
#define HID   64
#define NSTEP 10

typedef unsigned long long ull;

// Scratch: c_pre = b1 + context @ W1[2:66], layout [q][B] as float4 (q = neuron/4)
__device__ float4 g_cpre[16 * Bc];

// ---------- packed f32x2 helpers ----------
__device__ __forceinline__ ull pk2(float a, float b) {
    ull r; asm("mov.b64 %0, {%1, %2};" : "=l"(r) : "f"(a), "f"(b)); return r;
}
__device__ __forceinline__ void up2(ull v, float& a, float& b) {
    asm("mov.b64 {%0, %1}, %2;" : "=f"(a), "=f"(b) : "l"(v));
}
__device__ __forceinline__ ull ffma2(ull a, ull b, ull c) {
    ull d; asm("fma.rn.f32x2 %0, %1, %2, %3;" : "=l"(d) : "l"(a), "l"(b), "l"(c)); return d;
}
__device__ __forceinline__ ull fmul2(ull a, ull b) {
    ull d; asm("mul.rn.f32x2 %0, %1, %2;" : "=l"(d) : "l"(a), "l"(b)); return d;
}
__device__ __forceinline__ ull fadd2(ull a, ull b) {
    ull d; asm("add.rn.f32x2 %0, %1, %2;" : "=l"(d) : "l"(a), "l"(b)); return d;
}
__device__ __forceinline__ ull L64(const float* p) {        // LDS.64
    return *reinterpret_cast<const ull*>(p);
}
// tanh(x) = 1 - 2/(1 + exp(2x)); ex2.approx + rcp.approx. ~1e-7 abs err, saturates safely.
__device__ __forceinline__ float ftanh(float x) {
    float e; asm("ex2.approx.f32 %0, %1;" : "=f"(e) : "f"(x * 2.885390081777927f));
    float r; asm("rcp.approx.f32 %0, %1;" : "=f"(r) : "f"(e + 1.0f));
    return fmaf(-2.0f, r, 1.0f);
}

// ---------- Kernel A: c_pre precompute (context part of layer 1, done once) ----------
__global__ __launch_bounds__(256) void cnf_pre(
    const float* __restrict__ ctx, const float* __restrict__ W1,
    const float* __restrict__ b1)
{
    __shared__ __align__(16) float sW1c[64 * 64];  // W1 rows 2..65
    __shared__ float sb1[64];
    const int tid = threadIdx.x;
    for (int i = tid; i < 4096; i += 256) sW1c[i] = W1[2 * 64 + i];
    if (tid < 64) sb1[tid] = b1[tid];
    __syncthreads();

    const int b = blockIdx.x * 256 + tid;
    float cx[64];
    const float4* c4 = reinterpret_cast<const float4*>(ctx + (size_t)b * 64);
#pragma unroll
    for (int q = 0; q < 16; q++) {
        float4 v = __ldg(&c4[q]);
        cx[4 * q] = v.x; cx[4 * q + 1] = v.y; cx[4 * q + 2] = v.z; cx[4 * q + 3] = v.w;
    }
#pragma unroll 1
    for (int q = 0; q < 16; q++) {
        float4 a = make_float4(sb1[4 * q], sb1[4 * q + 1], sb1[4 * q + 2], sb1[4 * q + 3]);
#pragma unroll
        for (int c = 0; c < 64; c++) {
            const float4 w = *reinterpret_cast<const float4*>(&sW1c[(c << 6) + 4 * q]);
            a.x = fmaf(cx[c], w.x, a.x);
            a.y = fmaf(cx[c], w.y, a.y);
            a.z = fmaf(cx[c], w.z, a.z);
            a.w = fmaf(cx[c], w.w, a.w);
        }
        g_cpre[(size_t)q * Bc + b] = a;
    }
}

// ---------- Kernel B: RK4 CNF, forward-mode (JVP) Hutchinson, 2-way j-split ----------
// div = e^T (J e) via tangent propagation (one W2 pass per j-half):
//   s1[m]  = e0*W1[0,m] + e1*W1[1,m]
//   th1[m] = (1 - h1[m]^2) * s1[m]
//   u2[j]  = sum_m h1[m]*W2[m,j] ; t2[j] = sum_m th1[m]*W2[m,j]
//   f = tanh(u2)@W3 + b3 ;  Je = ((1-tanh(u2)^2)*t2)@W3 ;  div = e.Je
// j processed in two halves of 32 (accumulator file 16+16 ull = 64 regs ->
// 3 CTAs/SM). Layer 1 recomputed per half. q-loop unrolled x2 so two bodies'
// MUFU chains and W2 ffma2 blocks interleave.
__global__ __launch_bounds__(128, 3) void cnf_main(
    const float* __restrict__ x, const float* __restrict__ eps,
    const float* __restrict__ W1, const float* __restrict__ W2,
    const float* __restrict__ b2, const float* __restrict__ W3,
    const float* __restrict__ b3, float* __restrict__ out)
{
    __shared__ __align__(16) float sW2[64 * 64];   // [m][j]
    __shared__ __align__(16) float sW1r0[64];      // W1[0][j]
    __shared__ __align__(16) float sW1r1[64];      // W1[1][j]
    __shared__ __align__(16) float sW1t[64];       // W1[66][j]
    __shared__ __align__(16) float sb2[64];
    __shared__ __align__(16) float sW3[128];       // interleaved {W3[j][0], W3[j][1]}

    const int tid = threadIdx.x;
    {
        float4* d = reinterpret_cast<float4*>(sW2);
        const float4* s = reinterpret_cast<const float4*>(W2);
        for (int i = tid; i < 1024; i += 128) d[i] = s[i];
    }
    if (tid < 64) {
        sW1r0[tid] = W1[tid];
        sW1r1[tid] = W1[64 + tid];
        sW1t[tid]  = W1[66 * 64 + tid];
        sb2[tid]   = b2[tid];
        sW3[2 * tid]     = W3[2 * tid];
        sW3[2 * tid + 1] = W3[2 * tid + 1];
    }
    __syncthreads();

    const float bo0 = __ldg(&b3[0]), bo1 = __ldg(&b3[1]);
    const int b = blockIdx.x * 128 + tid;

    float z0 = x[2 * b], z1 = x[2 * b + 1], lp = 0.0f;
    const float step = -1.0f / 9.0f;

#pragma unroll 1
    for (int s = 0; s < NSTEP - 1; s++) {
        const float ti = 1.0f + s * step;
        const float hh = (1.0f + (s + 1) * step) - ti;
        float az0 = 0.f, az1 = 0.f, al = 0.f;
        float zi0 = z0, zi1 = z1;

#pragma unroll 1
        for (int k = 0; k < 4; k++) {
            const float tk = ti + ((k == 0) ? 0.0f : ((k == 3) ? hh : 0.5f * hh));
            const float2 ev = __ldg(reinterpret_cast<const float2*>(
                eps + (((size_t)(s * 4 + k)) * Bc + b) * 2));
            const float e0 = ev.x, e1 = ev.y;

            const ull z0d = pk2(zi0, zi0);
            const ull z1d = pk2(zi1, zi1);
            const ull tdp = pk2(tk, tk);
            const ull e0d = pk2(e0, e0);
            const ull e1d = pk2(e1, e1);

            ull fa0 = 0ULL, fa1 = 0ULL, ja0 = 0ULL, ja1 = 0ULL;

#pragma unroll 1
            for (int jh = 0; jh < 2; jh++) {
                const int jo = jh << 5;              // j offset (floats) of this half
                const float* w2h = sW2 + jo;

                // packed j-pair accumulators for this half: value + tangent
                ull accu[16], acct[16];
#pragma unroll
                for (int p = 0; p < 16; p++) {
                    accu[p] = L64(sb2 + jo + 2 * p);
                    acct[p] = 0ULL;
                }

                // fused layer 1 (recomputed per half) + rank-1 updates over half cols
#pragma unroll 2
                for (int q = 0; q < 16; q++) {
                    const float4 cp = __ldg(&g_cpre[(size_t)q * Bc + b]);
                    const ull r0a = L64(sW1r0 + 4 * q), r0b = L64(sW1r0 + 4 * q + 2);
                    const ull r1a = L64(sW1r1 + 4 * q), r1b = L64(sW1r1 + 4 * q + 2);
                    const ull tta = L64(sW1t  + 4 * q), ttb = L64(sW1t  + 4 * q + 2);
                    ull p0 = pk2(cp.x, cp.y), p1 = pk2(cp.z, cp.w);
                    p0 = ffma2(z0d, r0a, p0);  p1 = ffma2(z0d, r0b, p1);
                    p0 = ffma2(z1d, r1a, p0);  p1 = ffma2(z1d, r1b, p1);
                    p0 = ffma2(tdp, tta, p0);  p1 = ffma2(tdp, ttb, p1);
                    // layer-1 tangent: s1 = e0*W1r0 + e1*W1r1 (same operands)
                    ull sa = fmul2(e0d, r0a);  sa = ffma2(e1d, r1a, sa);
                    ull sb = fmul2(e0d, r0b);  sb = ffma2(e1d, r1b, sb);

                    float u4[4], s4[4];
                    up2(p0, u4[0], u4[1]); up2(p1, u4[2], u4[3]);
                    up2(sa, s4[0], s4[1]); up2(sb, s4[2], s4[3]);

                    // batch the 4 tanh chains up front so MUFU latency overlaps
                    // the ffma2 stream below
                    float h4[4], th4[4];
#pragma unroll
                    for (int r = 0; r < 4; r++) {
                        h4[r]  = ftanh(u4[r]);
                        th4[r] = s4[r] * fmaf(-h4[r], h4[r], 1.0f);
                    }

#pragma unroll
                    for (int r = 0; r < 4; r++) {
                        const int m = 4 * q + r;
                        const ull hd  = pk2(h4[r],  h4[r]);
                        const ull thd = pk2(th4[r], th4[r]);
                        const ulonglong2* wr =
                            reinterpret_cast<const ulonglong2*>(w2h + (m << 6));
#pragma unroll
                        for (int p = 0; p < 8; p++) {
                            const ulonglong2 wv = wr[p];    // LDS.128 broadcast
                            accu[2 * p]     = ffma2(hd,  wv.x, accu[2 * p]);
                            accu[2 * p + 1] = ffma2(hd,  wv.y, accu[2 * p + 1]);
                            acct[2 * p]     = ffma2(thd, wv.x, acct[2 * p]);
                            acct[2 * p + 1] = ffma2(thd, wv.y, acct[2 * p + 1]);
                        }
                    }
                }

                // output-layer epilogue for this half
                const float* w3h = sW3 + 2 * jo;
#pragma unroll
                for (int p = 0; p < 16; p++) {
                    float ua, ub; up2(accu[p], ua, ub);
                    float ta, tb; up2(acct[p], ta, tb);
                    const float ha = ftanh(ua), hb = ftanh(ub);
                    const float ca = ta * fmaf(-ha, ha, 1.0f);
                    const float cb = tb * fmaf(-hb, hb, 1.0f);
                    const ull w3a = L64(w3h + 4 * p);
                    const ull w3b = L64(w3h + 4 * p + 2);
                    fa0 = ffma2(pk2(ha, ha), w3a, fa0);
                    fa1 = ffma2(pk2(hb, hb), w3b, fa1);
                    ja0 = ffma2(pk2(ca, ca), w3a, ja0);
                    ja1 = ffma2(pk2(cb, cb), w3b, ja1);
                }
            }

            float f0, f1; up2(fadd2(fa0, fa1), f0, f1);
            f0 += bo0; f1 += bo1;
            float je0, je1; up2(fadd2(ja0, ja1), je0, je1);
            const float nd = -(je0 * e0 + je1 * e1);    // -divergence

            // ===== RK4 bookkeeping
            const float wk = (k == 1 || k == 2) ? 2.0f : 1.0f;
            az0 = fmaf(wk, f0, az0);
            az1 = fmaf(wk, f1, az1);
            al  = fmaf(wk, nd, al);
            const float cin = (k == 2) ? hh : 0.5f * hh;
            zi0 = fmaf(cin, f0, z0);
            zi1 = fmaf(cin, f1, z1);
        }
        const float c6 = hh * (1.0f / 6.0f);
        z0 = fmaf(c6, az0, z0);
        z1 = fmaf(c6, az1, z1);
        lp = fmaf(c6, al, lp);
    }

    out[2 * b]      = z0;
    out[2 * b + 1]  = z1;
    out[2 * Bc + b] = lp;          // lp1 follows flattened z1
}

extern "C" void kernel_launch(void* const* d_in, const int* in_sizes, int n_in,
                              void* d_out, int out_size)
{
    (void)in_sizes; (void)n_in; (void)out_size;
    const float* x   = (const float*)d_in[0];
    const float* ctx = (const float*)d_in[1];
    const float* eps = (const float*)d_in[2];
    const float* W1  = (const float*)d_in[3];
    const float* b1  = (const float*)d_in[4];
    const float* W2  = (const float*)d_in[5];
    const float* b2  = (const float*)d_in[6];
    const float* W3  = (const float*)d_in[7];
    const float* b3  = (const float*)d_in[8];
    float* out = (float*)d_out;

    cnf_pre<<<Bc / 256, 256>>>(ctx, W1, b1);
    cnf_main<<<Bc / 128, 128>>>(x, eps, W1, W2, b2, W3, b3, out);
}

// round 16
// speedup vs baseline: 1.2553x; 1.0448x over previous
#include <cuda_runtime.h>
#include <cstdint>

#define Bc    524288
#define HID   64
#define NSTEP 10

typedef unsigned long long ull;

// Scratch: c_pre = b1 + context @ W1[2:66], layout [q][B] as float4 (q = neuron/4)
__device__ float4 g_cpre[16 * Bc];

// ---------- packed f32x2 helpers ----------
__device__ __forceinline__ ull pk2(float a, float b) {
    ull r; asm("mov.b64 %0, {%1, %2};" : "=l"(r) : "f"(a), "f"(b)); return r;
}
__device__ __forceinline__ void up2(ull v, float& a, float& b) {
    asm("mov.b64 {%0, %1}, %2;" : "=f"(a), "=f"(b) : "l"(v));
}
__device__ __forceinline__ ull ffma2(ull a, ull b, ull c) {
    ull d; asm("fma.rn.f32x2 %0, %1, %2, %3;" : "=l"(d) : "l"(a), "l"(b), "l"(c)); return d;
}
__device__ __forceinline__ ull fmul2(ull a, ull b) {
    ull d; asm("mul.rn.f32x2 %0, %1, %2;" : "=l"(d) : "l"(a), "l"(b)); return d;
}
__device__ __forceinline__ ull fadd2(ull a, ull b) {
    ull d; asm("add.rn.f32x2 %0, %1, %2;" : "=l"(d) : "l"(a), "l"(b)); return d;
}
__device__ __forceinline__ ull L64(const float* p) {        // LDS.64
    return *reinterpret_cast<const ull*>(p);
}
// tanh(x) = 1 - 2/(1 + exp(2x)); ex2.approx + rcp.approx. ~1e-7 abs err, saturates safely.
__device__ __forceinline__ float ftanh(float x) {
    float e; asm("ex2.approx.f32 %0, %1;" : "=f"(e) : "f"(x * 2.885390081777927f));
    float r; asm("rcp.approx.f32 %0, %1;" : "=f"(r) : "f"(e + 1.0f));
    return fmaf(-2.0f, r, 1.0f);
}

// ---------- Kernel A: c_pre precompute (context part of layer 1, done once) ----------
__global__ __launch_bounds__(256) void cnf_pre(
    const float* __restrict__ ctx, const float* __restrict__ W1,
    const float* __restrict__ b1)
{
    __shared__ __align__(16) float sW1c[64 * 64];  // W1 rows 2..65
    __shared__ float sb1[64];
    const int tid = threadIdx.x;
    for (int i = tid; i < 4096; i += 256) sW1c[i] = W1[2 * 64 + i];
    if (tid < 64) sb1[tid] = b1[tid];
    __syncthreads();

    const int b = blockIdx.x * 256 + tid;
    float cx[64];
    const float4* c4 = reinterpret_cast<const float4*>(ctx + (size_t)b * 64);
#pragma unroll
    for (int q = 0; q < 16; q++) {
        float4 v = __ldg(&c4[q]);
        cx[4 * q] = v.x; cx[4 * q + 1] = v.y; cx[4 * q + 2] = v.z; cx[4 * q + 3] = v.w;
    }
#pragma unroll 1
    for (int q = 0; q < 16; q++) {
        float4 a = make_float4(sb1[4 * q], sb1[4 * q + 1], sb1[4 * q + 2], sb1[4 * q + 3]);
#pragma unroll
        for (int c = 0; c < 64; c++) {
            const float4 w = *reinterpret_cast<const float4*>(&sW1c[(c << 6) + 4 * q]);
            a.x = fmaf(cx[c], w.x, a.x);
            a.y = fmaf(cx[c], w.y, a.y);
            a.z = fmaf(cx[c], w.z, a.z);
            a.w = fmaf(cx[c], w.w, a.w);
        }
        g_cpre[(size_t)q * Bc + b] = a;
    }
}

// ---------- Kernel B: RK4 CNF, JVP Hutchinson, 2 samples/thread, 2-way j-split ------
// Each thread integrates TWO samples (bA, bB). All weight loads (W1 rows, W2 rows,
// W3, b2) are shared between the two samples: one LDS feeds both samples' ffma2
// chains, halving per-sample LDS traffic and doubling independent ILP so the
// fp32 FMA pipe (rt=2/SMSP) stays fed.
__global__ __launch_bounds__(128, 2) void cnf_main(
    const float* __restrict__ x, const float* __restrict__ eps,
    const float* __restrict__ W1, const float* __restrict__ W2,
    const float* __restrict__ b2, const float* __restrict__ W3,
    const float* __restrict__ b3, float* __restrict__ out)
{
    __shared__ __align__(16) float sW2[64 * 64];   // [m][j]
    __shared__ __align__(16) float sW1r0[64];      // W1[0][j]
    __shared__ __align__(16) float sW1r1[64];      // W1[1][j]
    __shared__ __align__(16) float sW1t[64];       // W1[66][j]
    __shared__ __align__(16) float sb2[64];
    __shared__ __align__(16) float sW3[128];       // interleaved {W3[j][0], W3[j][1]}

    const int tid = threadIdx.x;
    {
        float4* d = reinterpret_cast<float4*>(sW2);
        const float4* s = reinterpret_cast<const float4*>(W2);
        for (int i = tid; i < 1024; i += 128) d[i] = s[i];
    }
    if (tid < 64) {
        sW1r0[tid] = W1[tid];
        sW1r1[tid] = W1[64 + tid];
        sW1t[tid]  = W1[66 * 64 + tid];
        sb2[tid]   = b2[tid];
        sW3[2 * tid]     = W3[2 * tid];
        sW3[2 * tid + 1] = W3[2 * tid + 1];
    }
    __syncthreads();

    const float bo0 = __ldg(&b3[0]), bo1 = __ldg(&b3[1]);
    const int bA = blockIdx.x * 256 + tid;        // sample A
    const int bB = bA + 128;                      // sample B

    float z0A = x[2 * bA], z1A = x[2 * bA + 1], lpA = 0.0f;
    float z0B = x[2 * bB], z1B = x[2 * bB + 1], lpB = 0.0f;
    const float step = -1.0f / 9.0f;

#pragma unroll 1
    for (int s = 0; s < NSTEP - 1; s++) {
        const float ti = 1.0f + s * step;
        const float hh = (1.0f + (s + 1) * step) - ti;
        float az0A = 0.f, az1A = 0.f, alA = 0.f;
        float az0B = 0.f, az1B = 0.f, alB = 0.f;
        float zi0A = z0A, zi1A = z1A;
        float zi0B = z0B, zi1B = z1B;

#pragma unroll 1
        for (int k = 0; k < 4; k++) {
            const float tk = ti + ((k == 0) ? 0.0f : ((k == 3) ? hh : 0.5f * hh));
            const size_t eoff = ((size_t)(s * 4 + k)) * Bc;
            const float2 evA = __ldg(reinterpret_cast<const float2*>(eps + (eoff + bA) * 2));
            const float2 evB = __ldg(reinterpret_cast<const float2*>(eps + (eoff + bB) * 2));
            const float e0A = evA.x, e1A = evA.y;
            const float e0B = evB.x, e1B = evB.y;

            const ull tdp = pk2(tk, tk);

            ull fa0A = 0ULL, fa1A = 0ULL, ja0A = 0ULL, ja1A = 0ULL;
            ull fa0B = 0ULL, fa1B = 0ULL, ja0B = 0ULL, ja1B = 0ULL;

#pragma unroll 1
            for (int jh = 0; jh < 2; jh++) {
                const int jo = jh << 5;              // j offset (floats) of this half
                const float* w2h = sW2 + jo;

                // packed j-pair accumulators: value + tangent, per sample
                ull accuA[16], acctA[16], accuB[16], acctB[16];
#pragma unroll
                for (int p = 0; p < 16; p++) {
                    const ull bb = L64(sb2 + jo + 2 * p);
                    accuA[p] = bb; acctA[p] = 0ULL;
                    accuB[p] = bb; acctB[p] = 0ULL;
                }

                // fused layer 1 (both samples) + rank-1 updates over half cols
#pragma unroll 2
                for (int q = 0; q < 16; q++) {
                    const float4 cpA = __ldg(&g_cpre[(size_t)q * Bc + bA]);
                    const float4 cpB = __ldg(&g_cpre[(size_t)q * Bc + bB]);
                    const ull r0a = L64(sW1r0 + 4 * q), r0b = L64(sW1r0 + 4 * q + 2);
                    const ull r1a = L64(sW1r1 + 4 * q), r1b = L64(sW1r1 + 4 * q + 2);
                    const ull tta = L64(sW1t  + 4 * q), ttb = L64(sW1t  + 4 * q + 2);

                    // sample A pre-activations + tangent
                    ull pA0 = pk2(cpA.x, cpA.y), pA1 = pk2(cpA.z, cpA.w);
                    pA0 = ffma2(pk2(zi0A, zi0A), r0a, pA0);
                    pA1 = ffma2(pk2(zi0A, zi0A), r0b, pA1);
                    pA0 = ffma2(pk2(zi1A, zi1A), r1a, pA0);
                    pA1 = ffma2(pk2(zi1A, zi1A), r1b, pA1);
                    pA0 = ffma2(tdp, tta, pA0);
                    pA1 = ffma2(tdp, ttb, pA1);
                    ull sAa = fmul2(pk2(e0A, e0A), r0a); sAa = ffma2(pk2(e1A, e1A), r1a, sAa);
                    ull sAb = fmul2(pk2(e0A, e0A), r0b); sAb = ffma2(pk2(e1A, e1A), r1b, sAb);

                    // sample B pre-activations + tangent
                    ull pB0 = pk2(cpB.x, cpB.y), pB1 = pk2(cpB.z, cpB.w);
                    pB0 = ffma2(pk2(zi0B, zi0B), r0a, pB0);
                    pB1 = ffma2(pk2(zi0B, zi0B), r0b, pB1);
                    pB0 = ffma2(pk2(zi1B, zi1B), r1a, pB0);
                    pB1 = ffma2(pk2(zi1B, zi1B), r1b, pB1);
                    pB0 = ffma2(tdp, tta, pB0);
                    pB1 = ffma2(tdp, ttb, pB1);
                    ull sBa = fmul2(pk2(e0B, e0B), r0a); sBa = ffma2(pk2(e1B, e1B), r1a, sBa);
                    ull sBb = fmul2(pk2(e0B, e0B), r0b); sBb = ffma2(pk2(e1B, e1B), r1b, sBb);

                    float uA[4], sA[4], uB[4], sB[4];
                    up2(pA0, uA[0], uA[1]); up2(pA1, uA[2], uA[3]);
                    up2(sAa, sA[0], sA[1]); up2(sAb, sA[2], sA[3]);
                    up2(pB0, uB[0], uB[1]); up2(pB1, uB[2], uB[3]);
                    up2(sBa, sB[0], sB[1]); up2(sBb, sB[2], sB[3]);

                    // batch all 8 tanh chains so MUFU latency overlaps the ffma2 stream
                    float hA[4], thA[4], hB[4], thB[4];
#pragma unroll
                    for (int r = 0; r < 4; r++) {
                        hA[r]  = ftanh(uA[r]);
                        thA[r] = sA[r] * fmaf(-hA[r], hA[r], 1.0f);
                        hB[r]  = ftanh(uB[r]);
                        thB[r] = sB[r] * fmaf(-hB[r], hB[r], 1.0f);
                    }

#pragma unroll
                    for (int r = 0; r < 4; r++) {
                        const int m = 4 * q + r;
                        const ull hdA  = pk2(hA[r],  hA[r]);
                        const ull thdA = pk2(thA[r], thA[r]);
                        const ull hdB  = pk2(hB[r],  hB[r]);
                        const ull thdB = pk2(thB[r], thB[r]);
                        const ulonglong2* wr =
                            reinterpret_cast<const ulonglong2*>(w2h + (m << 6));
#pragma unroll
                        for (int p = 0; p < 8; p++) {
                            const ulonglong2 wv = wr[p];    // one LDS.128 feeds 8 ffma2
                            accuA[2 * p]     = ffma2(hdA,  wv.x, accuA[2 * p]);
                            accuA[2 * p + 1] = ffma2(hdA,  wv.y, accuA[2 * p + 1]);
                            acctA[2 * p]     = ffma2(thdA, wv.x, acctA[2 * p]);
                            acctA[2 * p + 1] = ffma2(thdA, wv.y, acctA[2 * p + 1]);
                            accuB[2 * p]     = ffma2(hdB,  wv.x, accuB[2 * p]);
                            accuB[2 * p + 1] = ffma2(hdB,  wv.y, accuB[2 * p + 1]);
                            acctB[2 * p]     = ffma2(thdB, wv.x, acctB[2 * p]);
                            acctB[2 * p + 1] = ffma2(thdB, wv.y, acctB[2 * p + 1]);
                        }
                    }
                }

                // output-layer epilogue for this half (W3 loads shared across samples)
                const float* w3h = sW3 + 2 * jo;
#pragma unroll
                for (int p = 0; p < 16; p++) {
                    const ull w3a = L64(w3h + 4 * p);
                    const ull w3b = L64(w3h + 4 * p + 2);
                    {
                        float ua, ub; up2(accuA[p], ua, ub);
                        float ta, tb; up2(acctA[p], ta, tb);
                        const float ha = ftanh(ua), hb = ftanh(ub);
                        const float ca = ta * fmaf(-ha, ha, 1.0f);
                        const float cb = tb * fmaf(-hb, hb, 1.0f);
                        fa0A = ffma2(pk2(ha, ha), w3a, fa0A);
                        fa1A = ffma2(pk2(hb, hb), w3b, fa1A);
                        ja0A = ffma2(pk2(ca, ca), w3a, ja0A);
                        ja1A = ffma2(pk2(cb, cb), w3b, ja1A);
                    }
                    {
                        float ua, ub; up2(accuB[p], ua, ub);
                        float ta, tb; up2(acctB[p], ta, tb);
                        const float ha = ftanh(ua), hb = ftanh(ub);
                        const float ca = ta * fmaf(-ha, ha, 1.0f);
                        const float cb = tb * fmaf(-hb, hb, 1.0f);
                        fa0B = ffma2(pk2(ha, ha), w3a, fa0B);
                        fa1B = ffma2(pk2(hb, hb), w3b, fa1B);
                        ja0B = ffma2(pk2(ca, ca), w3a, ja0B);
                        ja1B = ffma2(pk2(cb, cb), w3b, ja1B);
                    }
                }
            }

            float f0A, f1A; up2(fadd2(fa0A, fa1A), f0A, f1A);
            f0A += bo0; f1A += bo1;
            float je0A, je1A; up2(fadd2(ja0A, ja1A), je0A, je1A);
            const float ndA = -(je0A * e0A + je1A * e1A);

            float f0B, f1B; up2(fadd2(fa0B, fa1B), f0B, f1B);
            f0B += bo0; f1B += bo1;
            float je0B, je1B; up2(fadd2(ja0B, ja1B), je0B, je1B);
            const float ndB = -(je0B * e0B + je1B * e1B);

            // ===== RK4 bookkeeping (both samples)
            const float wk = (k == 1 || k == 2) ? 2.0f : 1.0f;
            az0A = fmaf(wk, f0A, az0A); az1A = fmaf(wk, f1A, az1A); alA = fmaf(wk, ndA, alA);
            az0B = fmaf(wk, f0B, az0B); az1B = fmaf(wk, f1B, az1B); alB = fmaf(wk, ndB, alB);
            const float cin = (k == 2) ? hh : 0.5f * hh;
            zi0A = fmaf(cin, f0A, z0A); zi1A = fmaf(cin, f1A, z1A);
            zi0B = fmaf(cin, f0B, z0B); zi1B = fmaf(cin, f1B, z1B);
        }
        const float c6 = hh * (1.0f / 6.0f);
        z0A = fmaf(c6, az0A, z0A); z1A = fmaf(c6, az1A, z1A); lpA = fmaf(c6, alA, lpA);
        z0B = fmaf(c6, az0B, z0B); z1B = fmaf(c6, az1B, z1B); lpB = fmaf(c6, alB, lpB);
    }

    out[2 * bA]      = z0A;
    out[2 * bA + 1]  = z1A;
    out[2 * Bc + bA] = lpA;
    out[2 * bB]      = z0B;
    out[2 * bB + 1]  = z1B;
    out[2 * Bc + bB] = lpB;
}

extern "C" void kernel_launch(void* const* d_in, const int* in_sizes, int n_in,
                              void* d_out, int out_size)
{
    (void)in_sizes; (void)n_in; (void)out_size;
    const float* x   = (const float*)d_in[0];
    const float* ctx = (const float*)d_in[1];
    const float* eps = (const float*)d_in[2];
    const float* W1  = (const float*)d_in[3];
    const float* b1  = (const float*)d_in[4];
    const float* W2  = (const float*)d_in[5];
    const float* b2  = (const float*)d_in[6];
    const float* W3  = (const float*)d_in[7];
    const float* b3  = (const float*)d_in[8];
    float* out = (float*)d_out;

    cnf_pre<<<Bc / 256, 256>>>(ctx, W1, b1);
    cnf_main<<<Bc / 256, 128>>>(x, eps, W1, W2, b2, W3, b3, out);
}

// round 17
// speedup vs baseline: 1.4736x; 1.1739x over previous
#include <cuda_runtime.h>
#include <cstdint>

#define Bc    524288
#define HID   64
#define NSTEP 10

typedef unsigned long long ull;

// Scratch: c_pre = b1 + context @ W1[2:66], layout [q][B] as float4 (q = neuron/4)
__device__ float4 g_cpre[16 * Bc];

// ---------- packed f32x2 helpers ----------
__device__ __forceinline__ ull pk2(float a, float b) {
    ull r; asm("mov.b64 %0, {%1, %2};" : "=l"(r) : "f"(a), "f"(b)); return r;
}
__device__ __forceinline__ void up2(ull v, float& a, float& b) {
    asm("mov.b64 {%0, %1}, %2;" : "=f"(a), "=f"(b) : "l"(v));
}
__device__ __forceinline__ ull ffma2(ull a, ull b, ull c) {
    ull d; asm("fma.rn.f32x2 %0, %1, %2, %3;" : "=l"(d) : "l"(a), "l"(b), "l"(c)); return d;
}
__device__ __forceinline__ ull fmul2(ull a, ull b) {
    ull d; asm("mul.rn.f32x2 %0, %1, %2;" : "=l"(d) : "l"(a), "l"(b)); return d;
}
__device__ __forceinline__ ull fadd2(ull a, ull b) {
    ull d; asm("add.rn.f32x2 %0, %1, %2;" : "=l"(d) : "l"(a), "l"(b)); return d;
}
__device__ __forceinline__ ull L64(const float* p) {        // LDS.64
    return *reinterpret_cast<const ull*>(p);
}
// Native MUFU tanh (sm_75+): single instruction, ~5e-4 worst-case abs err.
__device__ __forceinline__ float ftanh(float x) {
    float r; asm("tanh.approx.f32 %0, %1;" : "=f"(r) : "f"(x));
    return r;
}

// ---------- Kernel A: c_pre precompute (context part of layer 1, done once) ----------
__global__ __launch_bounds__(256) void cnf_pre(
    const float* __restrict__ ctx, const float* __restrict__ W1,
    const float* __restrict__ b1)
{
    __shared__ __align__(16) float sW1c[64 * 64];  // W1 rows 2..65
    __shared__ float sb1[64];
    const int tid = threadIdx.x;
    for (int i = tid; i < 4096; i += 256) sW1c[i] = W1[2 * 64 + i];
    if (tid < 64) sb1[tid] = b1[tid];
    __syncthreads();

    const int b = blockIdx.x * 256 + tid;
    float cx[64];
    const float4* c4 = reinterpret_cast<const float4*>(ctx + (size_t)b * 64);
#pragma unroll
    for (int q = 0; q < 16; q++) {
        float4 v = __ldg(&c4[q]);
        cx[4 * q] = v.x; cx[4 * q + 1] = v.y; cx[4 * q + 2] = v.z; cx[4 * q + 3] = v.w;
    }
#pragma unroll 1
    for (int q = 0; q < 16; q++) {
        float4 a = make_float4(sb1[4 * q], sb1[4 * q + 1], sb1[4 * q + 2], sb1[4 * q + 3]);
#pragma unroll
        for (int c = 0; c < 64; c++) {
            const float4 w = *reinterpret_cast<const float4*>(&sW1c[(c << 6) + 4 * q]);
            a.x = fmaf(cx[c], w.x, a.x);
            a.y = fmaf(cx[c], w.y, a.y);
            a.z = fmaf(cx[c], w.z, a.z);
            a.w = fmaf(cx[c], w.w, a.w);
        }
        g_cpre[(size_t)q * Bc + b] = a;
    }
}

// ---------- Kernel B: RK4 CNF, JVP Hutchinson, 2 samples/thread, 2-way j-split ------
// Each thread integrates TWO samples (bA, bB). All weight loads (W1 rows, W2 rows,
// W3, b2) are shared between the two samples: one LDS feeds both samples' ffma2
// chains, halving per-sample LDS traffic and doubling independent ILP so the
// fp32 FMA pipe (rt=2/SMSP) stays fed. tanh via single-op MUFU.TANH.
__global__ __launch_bounds__(128, 2) void cnf_main(
    const float* __restrict__ x, const float* __restrict__ eps,
    const float* __restrict__ W1, const float* __restrict__ W2,
    const float* __restrict__ b2, const float* __restrict__ W3,
    const float* __restrict__ b3, float* __restrict__ out)
{
    __shared__ __align__(16) float sW2[64 * 64];   // [m][j]
    __shared__ __align__(16) float sW1r0[64];      // W1[0][j]
    __shared__ __align__(16) float sW1r1[64];      // W1[1][j]
    __shared__ __align__(16) float sW1t[64];       // W1[66][j]
    __shared__ __align__(16) float sb2[64];
    __shared__ __align__(16) float sW3[128];       // interleaved {W3[j][0], W3[j][1]}

    const int tid = threadIdx.x;
    {
        float4* d = reinterpret_cast<float4*>(sW2);
        const float4* s = reinterpret_cast<const float4*>(W2);
        for (int i = tid; i < 1024; i += 128) d[i] = s[i];
    }
    if (tid < 64) {
        sW1r0[tid] = W1[tid];
        sW1r1[tid] = W1[64 + tid];
        sW1t[tid]  = W1[66 * 64 + tid];
        sb2[tid]   = b2[tid];
        sW3[2 * tid]     = W3[2 * tid];
        sW3[2 * tid + 1] = W3[2 * tid + 1];
    }
    __syncthreads();

    const float bo0 = __ldg(&b3[0]), bo1 = __ldg(&b3[1]);
    const int bA = blockIdx.x * 256 + tid;        // sample A
    const int bB = bA + 128;                      // sample B

    float z0A = x[2 * bA], z1A = x[2 * bA + 1], lpA = 0.0f;
    float z0B = x[2 * bB], z1B = x[2 * bB + 1], lpB = 0.0f;
    const float step = -1.0f / 9.0f;

#pragma unroll 1
    for (int s = 0; s < NSTEP - 1; s++) {
        const float ti = 1.0f + s * step;
        const float hh = (1.0f + (s + 1) * step) - ti;
        float az0A = 0.f, az1A = 0.f, alA = 0.f;
        float az0B = 0.f, az1B = 0.f, alB = 0.f;
        float zi0A = z0A, zi1A = z1A;
        float zi0B = z0B, zi1B = z1B;

#pragma unroll 1
        for (int k = 0; k < 4; k++) {
            const float tk = ti + ((k == 0) ? 0.0f : ((k == 3) ? hh : 0.5f * hh));
            const size_t eoff = ((size_t)(s * 4 + k)) * Bc;
            const float2 evA = __ldg(reinterpret_cast<const float2*>(eps + (eoff + bA) * 2));
            const float2 evB = __ldg(reinterpret_cast<const float2*>(eps + (eoff + bB) * 2));
            const float e0A = evA.x, e1A = evA.y;
            const float e0B = evB.x, e1B = evB.y;

            const ull tdp = pk2(tk, tk);

            ull fa0A = 0ULL, fa1A = 0ULL, ja0A = 0ULL, ja1A = 0ULL;
            ull fa0B = 0ULL, fa1B = 0ULL, ja0B = 0ULL, ja1B = 0ULL;

#pragma unroll 1
            for (int jh = 0; jh < 2; jh++) {
                const int jo = jh << 5;              // j offset (floats) of this half
                const float* w2h = sW2 + jo;

                // packed j-pair accumulators: value + tangent, per sample
                ull accuA[16], acctA[16], accuB[16], acctB[16];
#pragma unroll
                for (int p = 0; p < 16; p++) {
                    const ull bb = L64(sb2 + jo + 2 * p);
                    accuA[p] = bb; acctA[p] = 0ULL;
                    accuB[p] = bb; acctB[p] = 0ULL;
                }

                // fused layer 1 (both samples) + rank-1 updates over half cols
#pragma unroll 2
                for (int q = 0; q < 16; q++) {
                    const float4 cpA = __ldg(&g_cpre[(size_t)q * Bc + bA]);
                    const float4 cpB = __ldg(&g_cpre[(size_t)q * Bc + bB]);
                    const ull r0a = L64(sW1r0 + 4 * q), r0b = L64(sW1r0 + 4 * q + 2);
                    const ull r1a = L64(sW1r1 + 4 * q), r1b = L64(sW1r1 + 4 * q + 2);
                    const ull tta = L64(sW1t  + 4 * q), ttb = L64(sW1t  + 4 * q + 2);

                    // sample A pre-activations + tangent
                    ull pA0 = pk2(cpA.x, cpA.y), pA1 = pk2(cpA.z, cpA.w);
                    pA0 = ffma2(pk2(zi0A, zi0A), r0a, pA0);
                    pA1 = ffma2(pk2(zi0A, zi0A), r0b, pA1);
                    pA0 = ffma2(pk2(zi1A, zi1A), r1a, pA0);
                    pA1 = ffma2(pk2(zi1A, zi1A), r1b, pA1);
                    pA0 = ffma2(tdp, tta, pA0);
                    pA1 = ffma2(tdp, ttb, pA1);
                    ull sAa = fmul2(pk2(e0A, e0A), r0a); sAa = ffma2(pk2(e1A, e1A), r1a, sAa);
                    ull sAb = fmul2(pk2(e0A, e0A), r0b); sAb = ffma2(pk2(e1A, e1A), r1b, sAb);

                    // sample B pre-activations + tangent
                    ull pB0 = pk2(cpB.x, cpB.y), pB1 = pk2(cpB.z, cpB.w);
                    pB0 = ffma2(pk2(zi0B, zi0B), r0a, pB0);
                    pB1 = ffma2(pk2(zi0B, zi0B), r0b, pB1);
                    pB0 = ffma2(pk2(zi1B, zi1B), r1a, pB0);
                    pB1 = ffma2(pk2(zi1B, zi1B), r1b, pB1);
                    pB0 = ffma2(tdp, tta, pB0);
                    pB1 = ffma2(tdp, ttb, pB1);
                    ull sBa = fmul2(pk2(e0B, e0B), r0a); sBa = ffma2(pk2(e1B, e1B), r1a, sBa);
                    ull sBb = fmul2(pk2(e0B, e0B), r0b); sBb = ffma2(pk2(e1B, e1B), r1b, sBb);

                    float uA[4], sA[4], uB[4], sB[4];
                    up2(pA0, uA[0], uA[1]); up2(pA1, uA[2], uA[3]);
                    up2(sAa, sA[0], sA[1]); up2(sAb, sA[2], sA[3]);
                    up2(pB0, uB[0], uB[1]); up2(pB1, uB[2], uB[3]);
                    up2(sBa, sB[0], sB[1]); up2(sBb, sB[2], sB[3]);

                    // batch all 8 tanh (single MUFU.TANH each) so latency overlaps
                    float hA[4], thA[4], hB[4], thB[4];
#pragma unroll
                    for (int r = 0; r < 4; r++) {
                        hA[r]  = ftanh(uA[r]);
                        thA[r] = sA[r] * fmaf(-hA[r], hA[r], 1.0f);
                        hB[r]  = ftanh(uB[r]);
                        thB[r] = sB[r] * fmaf(-hB[r], hB[r], 1.0f);
                    }

#pragma unroll
                    for (int r = 0; r < 4; r++) {
                        const int m = 4 * q + r;
                        const ull hdA  = pk2(hA[r],  hA[r]);
                        const ull thdA = pk2(thA[r], thA[r]);
                        const ull hdB  = pk2(hB[r],  hB[r]);
                        const ull thdB = pk2(thB[r], thB[r]);
                        const ulonglong2* wr =
                            reinterpret_cast<const ulonglong2*>(w2h + (m << 6));
#pragma unroll
                        for (int p = 0; p < 8; p++) {
                            const ulonglong2 wv = wr[p];    // one LDS.128 feeds 8 ffma2
                            accuA[2 * p]     = ffma2(hdA,  wv.x, accuA[2 * p]);
                            accuA[2 * p + 1] = ffma2(hdA,  wv.y, accuA[2 * p + 1]);
                            acctA[2 * p]     = ffma2(thdA, wv.x, acctA[2 * p]);
                            acctA[2 * p + 1] = ffma2(thdA, wv.y, acctA[2 * p + 1]);
                            accuB[2 * p]     = ffma2(hdB,  wv.x, accuB[2 * p]);
                            accuB[2 * p + 1] = ffma2(hdB,  wv.y, accuB[2 * p + 1]);
                            acctB[2 * p]     = ffma2(thdB, wv.x, acctB[2 * p]);
                            acctB[2 * p + 1] = ffma2(thdB, wv.y, acctB[2 * p + 1]);
                        }
                    }
                }

                // output-layer epilogue for this half (W3 loads shared across samples)
                const float* w3h = sW3 + 2 * jo;
#pragma unroll
                for (int p = 0; p < 16; p++) {
                    const ull w3a = L64(w3h + 4 * p);
                    const ull w3b = L64(w3h + 4 * p + 2);
                    {
                        float ua, ub; up2(accuA[p], ua, ub);
                        float ta, tb; up2(acctA[p], ta, tb);
                        const float ha = ftanh(ua), hb = ftanh(ub);
                        const float ca = ta * fmaf(-ha, ha, 1.0f);
                        const float cb = tb * fmaf(-hb, hb, 1.0f);
                        fa0A = ffma2(pk2(ha, ha), w3a, fa0A);
                        fa1A = ffma2(pk2(hb, hb), w3b, fa1A);
                        ja0A = ffma2(pk2(ca, ca), w3a, ja0A);
                        ja1A = ffma2(pk2(cb, cb), w3b, ja1A);
                    }
                    {
                        float ua, ub; up2(accuB[p], ua, ub);
                        float ta, tb; up2(acctB[p], ta, tb);
                        const float ha = ftanh(ua), hb = ftanh(ub);
                        const float ca = ta * fmaf(-ha, ha, 1.0f);
                        const float cb = tb * fmaf(-hb, hb, 1.0f);
                        fa0B = ffma2(pk2(ha, ha), w3a, fa0B);
                        fa1B = ffma2(pk2(hb, hb), w3b, fa1B);
                        ja0B = ffma2(pk2(ca, ca), w3a, ja0B);
                        ja1B = ffma2(pk2(cb, cb), w3b, ja1B);
                    }
                }
            }

            float f0A, f1A; up2(fadd2(fa0A, fa1A), f0A, f1A);
            f0A += bo0; f1A += bo1;
            float je0A, je1A; up2(fadd2(ja0A, ja1A), je0A, je1A);
            const float ndA = -(je0A * e0A + je1A * e1A);

            float f0B, f1B; up2(fadd2(fa0B, fa1B), f0B, f1B);
            f0B += bo0; f1B += bo1;
            float je0B, je1B; up2(fadd2(ja0B, ja1B), je0B, je1B);
            const float ndB = -(je0B * e0B + je1B * e1B);

            // ===== RK4 bookkeeping (both samples)
            const float wk = (k == 1 || k == 2) ? 2.0f : 1.0f;
            az0A = fmaf(wk, f0A, az0A); az1A = fmaf(wk, f1A, az1A); alA = fmaf(wk, ndA, alA);
            az0B = fmaf(wk, f0B, az0B); az1B = fmaf(wk, f1B, az1B); alB = fmaf(wk, ndB, alB);
            const float cin = (k == 2) ? hh : 0.5f * hh;
            zi0A = fmaf(cin, f0A, z0A); zi1A = fmaf(cin, f1A, z1A);
            zi0B = fmaf(cin, f0B, z0B); zi1B = fmaf(cin, f1B, z1B);
        }
        const float c6 = hh * (1.0f / 6.0f);
        z0A = fmaf(c6, az0A, z0A); z1A = fmaf(c6, az1A, z1A); lpA = fmaf(c6, alA, lpA);
        z0B = fmaf(c6, az0B, z0B); z1B = fmaf(c6, az1B, z1B); lpB = fmaf(c6, alB, lpB);
    }

    out[2 * bA]      = z0A;
    out[2 * bA + 1]  = z1A;
    out[2 * Bc + bA] = lpA;
    out[2 * bB]      = z0B;
    out[2 * bB + 1]  = z1B;
    out[2 * Bc + bB] = lpB;
}

extern "C" void kernel_launch(void* const* d_in, const int* in_sizes, int n_in,
                              void* d_out, int out_size)
{
    (void)in_sizes; (void)n_in; (void)out_size;
    const float* x   = (const float*)d_in[0];
    const float* ctx = (const float*)d_in[1];
    const float* eps = (const float*)d_in[2];
    const float* W1  = (const float*)d_in[3];
    const float* b1  = (const float*)d_in[4];
    const float* W2  = (const float*)d_in[5];
    const float* b2  = (const float*)d_in[6];
    const float* W3  = (const float*)d_in[7];
    const float* b3  = (const float*)d_in[8];
    float* out = (float*)d_out;

    cnf_pre<<<Bc / 256, 256>>>(ctx, W1, b1);
    cnf_main<<<Bc / 256, 128>>>(x, eps, W1, W2, b2, W3, b3, out);
}